// round 1
// baseline (speedup 1.0000x reference)
#include <cuda_runtime.h>

#define NB      128     // persistent CTAs (< 148 SMs -> co-resident, barrier safe)
#define THREADS 256
#define BB      64      // batch
#define SS      2048    // seq len
#define HH      512     // hidden
#define VV      25      // vocab

// h double buffer: [parity][k][batch-slot], slot = rank in sorted-by-length order
__device__ float g_h[2][HH * BB];
__device__ unsigned g_count;
__device__ volatile unsigned g_phase;

__global__ void init_barrier_kernel() {
    g_count = 0u;
    g_phase = 0u;
}

// packed fp32x2 FMA (Blackwell): acc += x * y elementwise on 2 lanes
__device__ __forceinline__ void ffma2(float2& a, const float2 x, const float2 y) {
    asm("fma.rn.f32x2 %0, %1, %2, %0;"
        : "+l"(reinterpret_cast<unsigned long long&>(a))
        : "l"(reinterpret_cast<const unsigned long long&>(x)),
          "l"(reinterpret_cast<const unsigned long long&>(y)));
}

__device__ __forceinline__ float sigmoidf_(float x) {
    return 1.f / (1.f + expf(-x));
}

// monotonic-phase grid barrier (no counter reset mid-kernel; init kernel zeroes state)
__device__ __forceinline__ void grid_barrier(int tid, unsigned barno) {
    __syncthreads();
    if (tid == 0) {
        __threadfence();
        unsigned v = atomicAdd(&g_count, 1u);
        if (v + 1u == barno * (unsigned)NB) {
            __threadfence();
            g_phase = barno;
        } else {
            while (g_phase < barno) { }
        }
        __threadfence();
    }
    __syncthreads();
}

// dynamic smem layout sizes (bytes)
#define WSP_BYTES  (HH * 16 * 8)        // [512][16] float2 packed {w,w}  = 65536
#define RED_BYTES  (8 * 16 * 32 * 8)    // [warp][gate-row][bp] float2    = 32768
#define WXB_BYTES  (16 * 32 * 4)        // [gate-row][vocab padded 32]    = 2048
#define GRED_BYTES (16 * 64 * 4)        // reduced gates [row][batch]     = 4096
#define CS_BYTES   (4 * 64 * 4)         // cell state [j][batch]          = 1024
#define INT_BYTES  (3 * 64 * 4)         // slen, sorder, lens             = 768
#define SMEM_BYTES (WSP_BYTES + RED_BYTES + WXB_BYTES + GRED_BYTES + CS_BYTES + INT_BYTES)

__global__ void __launch_bounds__(THREADS, 1) lstm_persistent_kernel(
    const int* __restrict__ tokens, const int* __restrict__ lengths,
    const float* __restrict__ W_ih, const float* __restrict__ W_hh,
    const float* __restrict__ b_ih, const float* __restrict__ b_hh,
    const float* __restrict__ fc_w, const float* __restrict__ fc_b,
    float* __restrict__ out)
{
    extern __shared__ char smem_raw[];
    float2* wsp  = reinterpret_cast<float2*>(smem_raw);
    float2* red  = reinterpret_cast<float2*>(smem_raw + WSP_BYTES);
    float*  wxb  = reinterpret_cast<float*>(smem_raw + WSP_BYTES + RED_BYTES);
    float*  gred = wxb + 16 * 32;
    float*  cs   = gred + 16 * 64;
    int*    slen   = reinterpret_cast<int*>(cs + 4 * 64);
    int*    sorder = slen + 64;
    int*    lens   = sorder + 64;

    const int tid = threadIdx.x;
    const int c4  = blockIdx.x * 4;   // this CTA's 4 hidden dims: c4 .. c4+3

    // ---- load W_hh chunk, packed {w,w}, layout wsp[k][r], r = gate*4 + j ----
    for (int idx = tid; idx < 16 * HH; idx += THREADS) {
        int r = idx / HH, k = idx - r * HH;            // k fast -> coalesced global read
        int R = (r >> 2) * HH + c4 + (r & 3);          // global gate row
        float w = W_hh[R * HH + k];
        wsp[k * 16 + r] = make_float2(w, w);
    }
    // ---- W_ih chunk folded with biases: wxb[r][v] = W_ih[R][v] + b_ih[R] + b_hh[R] ----
    for (int idx = tid; idx < 16 * VV; idx += THREADS) {
        int r = idx / VV, v = idx - r * VV;
        int R = (r >> 2) * HH + c4 + (r & 3);
        wxb[r * 32 + v] = W_ih[R * VV + v] + b_ih[R] + b_hh[R];
    }
    // ---- stable descending argsort of lengths (B=64, O(B^2)) ----
    if (tid < BB) lens[tid] = lengths[tid];
    __syncthreads();
    if (tid < BB) {
        int L = lens[tid], rk = 0;
        for (int b2 = 0; b2 < BB; b2++) {
            int L2 = lens[b2];
            rk += (L2 > L) || (L2 == L && b2 < tid);
        }
        sorder[rk] = tid;
        slen[rk]   = L;
    }
    // ---- zero c state and this CTA's rows of h buffer 0 ----
    for (int idx = tid; idx < 4 * BB; idx += THREADS) {
        cs[idx] = 0.f;
        g_h[0][(c4 + (idx >> 6)) * BB + (idx & 63)] = 0.f;
    }
    __syncthreads();
    const int T = slen[0];   // max length (same in every CTA)

    unsigned barno = 1;
    grid_barrier(tid, barno);   // all init (incl. h zeros) visible before step 0

    const int w = tid >> 5, l = tid & 31;
    const int kbase = w * 64;

    for (int t = 0; t < T; t++) {
        const float* hr = g_h[t & 1];
        float*       hw = g_h[(t & 1) ^ 1];

        // ---- recurrent matmul partials: warp = k-slice(64), lane = batch-pair ----
        {
            const float2* hp = reinterpret_cast<const float2*>(hr) + l;  // elem k*32 + l
            float2 acc[16];
#pragma unroll
            for (int r = 0; r < 16; r++) acc[r] = make_float2(0.f, 0.f);
#pragma unroll 4
            for (int kk = 0; kk < 64; kk++) {
                const int k = kbase + kk;
                float2 h2 = __ldcg(hp + k * 32);       // L2-coherent (cross-SM producer)
                const float4* wrow = reinterpret_cast<const float4*>(wsp + k * 16);
#pragma unroll
                for (int q = 0; q < 8; q++) {
                    float4 w4 = wrow[q];               // {w_{2q},w_{2q},w_{2q+1},w_{2q+1}}
                    ffma2(acc[2 * q],     h2, make_float2(w4.x, w4.y));
                    ffma2(acc[2 * q + 1], h2, make_float2(w4.z, w4.w));
                }
            }
#pragma unroll
            for (int r = 0; r < 16; r++) red[(w * 16 + r) * 32 + l] = acc[r];
        }
        __syncthreads();

        // ---- deterministic cross-warp reduction: 512 float2 outputs, 2/thread ----
        for (int o = tid; o < 512; o += THREADS) {
            int r = o >> 5, bp = o & 31;
            float2 sacc = red[r * 32 + bp];
#pragma unroll
            for (int w2 = 1; w2 < 8; w2++) {
                float2 v2 = red[(w2 * 16 + r) * 32 + bp];
                sacc.x += v2.x; sacc.y += v2.y;
            }
            gred[r * 64 + 2 * bp]     = sacc.x;
            gred[r * 64 + 2 * bp + 1] = sacc.y;
        }
        __syncthreads();

        // ---- gate activations + state update: thread = (j in 0..3, batch-slot b) ----
        {
            int j = tid >> 6, b = tid & 63;
            int kidx = c4 + j;
            if (t < slen[b]) {
                int tok = __ldg(&tokens[sorder[b] * SS + t]);
                float gi = gred[(j)      * 64 + b] + wxb[(j)      * 32 + tok];
                float gf = gred[(4 + j)  * 64 + b] + wxb[(4 + j)  * 32 + tok];
                float gg = gred[(8 + j)  * 64 + b] + wxb[(8 + j)  * 32 + tok];
                float go = gred[(12 + j) * 64 + b] + wxb[(12 + j) * 32 + tok];
                float ig = sigmoidf_(gi);
                float fg = sigmoidf_(gf);
                float gv = tanhf(gg);
                float og = sigmoidf_(go);
                float cn = fg * cs[j * 64 + b] + ig * gv;
                cs[j * 64 + b] = cn;
                __stcg(&hw[kidx * BB + b], og * tanhf(cn));
            } else {
                // frozen sequence: carry h forward so the next parity buffer is complete
                __stcg(&hw[kidx * BB + b], __ldcg(&hr[kidx * BB + b]));
            }
        }

        barno++;
        grid_barrier(tid, barno);
    }

    // ---- final FC: out[s] = fc_w . h_final[:, s] + fc_b (sorted order) ----
    if (blockIdx.x == 0) {
        const float* hf = g_h[T & 1];
        int s = tid >> 2, q = tid & 3;
        float p = 0.f;
        for (int kk = 0; kk < 128; kk++) {
            int k = q * 128 + kk;
            p += __ldcg(&hf[k * BB + s]) * __ldg(&fc_w[k]);
        }
        p += __shfl_down_sync(0xffffffffu, p, 1);
        p += __shfl_down_sync(0xffffffffu, p, 2);
        if (q == 0) out[s] = p + __ldg(fc_b);
    }
}

extern "C" void kernel_launch(void* const* d_in, const int* in_sizes, int n_in,
                              void* d_out, int out_size) {
    const int*   tokens  = (const int*)d_in[0];
    const int*   lengths = (const int*)d_in[1];
    const float* W_ih    = (const float*)d_in[2];
    const float* W_hh    = (const float*)d_in[3];
    const float* b_ih    = (const float*)d_in[4];
    const float* b_hh    = (const float*)d_in[5];
    const float* fc_w    = (const float*)d_in[6];
    const float* fc_b    = (const float*)d_in[7];
    float* out = (float*)d_out;

    cudaFuncSetAttribute(lstm_persistent_kernel,
                         cudaFuncAttributeMaxDynamicSharedMemorySize, SMEM_BYTES);
    init_barrier_kernel<<<1, 1>>>();
    lstm_persistent_kernel<<<NB, THREADS, SMEM_BYTES>>>(
        tokens, lengths, W_ih, W_hh, b_ih, b_hh, fc_w, fc_b, out);
}

// round 2
// speedup vs baseline: 1.3417x; 1.3417x over previous
#include <cuda_runtime.h>

#define NB      128     // persistent CTAs (< 148 SMs -> co-resident, barrier safe)
#define THREADS 512     // 16 warps, 4 per SMSP
#define BB      64      // batch
#define SS      2048    // seq len
#define HH      512     // hidden
#define VV      25      // vocab

// h double buffer, batch-duplicated: [parity][k][2*BB], slot 2b,2b+1 both = h[k][b]
__device__ float g_hdup[2][HH * 2 * BB];
__device__ unsigned g_count;
__device__ volatile unsigned g_phase;

__global__ void init_barrier_kernel() {
    g_count = 0u;
    g_phase = 0u;
}

// packed fp32x2 FMA (Blackwell): acc += x * y elementwise on 2 lanes
__device__ __forceinline__ void ffma2(float2& a, const float2 x, const float2 y) {
    asm("fma.rn.f32x2 %0, %1, %2, %0;"
        : "+l"(reinterpret_cast<unsigned long long&>(a))
        : "l"(reinterpret_cast<const unsigned long long&>(x)),
          "l"(reinterpret_cast<const unsigned long long&>(y)));
}

// fast, saturation-safe sigmoid / tanh (EX2+RCP based, ~1e-7 abs err)
__device__ __forceinline__ float sigm(float x) {
    float e = __expf(-x);                 // x<<0 -> inf, x>>0 -> 0 (both safe)
    return __fdividef(1.f, 1.f + e);
}
__device__ __forceinline__ float tanha(float x) {
    return fmaf(2.f, sigm(2.f * x), -1.f);
}

// monotonic-phase grid barrier
__device__ __forceinline__ void grid_barrier(int tid, unsigned barno) {
    __syncthreads();
    if (tid == 0) {
        __threadfence();
        unsigned v = atomicAdd(&g_count, 1u);
        if (v + 1u == barno * (unsigned)NB) {
            __threadfence();
            g_phase = barno;
        } else {
            while (g_phase < barno) { }
        }
        __threadfence();
    }
    __syncthreads();
}

// dynamic smem layout (bytes)
#define WSP_FLOATS  (HH * 20)          // [k][20]: 16 rows (r=gate*4+j order) + 4 pad
#define WXB_FLOATS  (16 * 32)          // [r][vocab padded 32], biases folded
#define GRD_FLOATS  (2 * BB * 20)      // [kh][batch][20]: 16 gate rows + pad
#define SMEM_BYTES  ((WSP_FLOATS + WXB_FLOATS + GRD_FLOATS + 3 * BB) * 4)

__global__ void __launch_bounds__(THREADS, 1) lstm_persistent_kernel(
    const int* __restrict__ tokens, const int* __restrict__ lengths,
    const float* __restrict__ W_ih, const float* __restrict__ W_hh,
    const float* __restrict__ b_ih, const float* __restrict__ b_hh,
    const float* __restrict__ fc_w, const float* __restrict__ fc_b,
    float* __restrict__ out)
{
    extern __shared__ char smem_raw[];
    float* wsp   = reinterpret_cast<float*>(smem_raw);
    float* wxb   = wsp + WSP_FLOATS;
    float* gredp = wxb + WXB_FLOATS;              // [kh*64*20 + b*20 + r]
    int*   slen   = reinterpret_cast<int*>(gredp + GRD_FLOATS);
    int*   sorder = slen + BB;
    int*   lens   = sorder + BB;

    const int tid = threadIdx.x;
    const int c4  = blockIdx.x * 4;   // this CTA's 4 hidden dims

    // ---- W_hh chunk into smem: wsp[k*20 + r], r = gate*4 + j ----
    for (int idx = tid; idx < 16 * HH; idx += THREADS) {
        int r = idx >> 9, k = idx & (HH - 1);
        int R = (r >> 2) * HH + c4 + (r & 3);
        wsp[k * 20 + r] = W_hh[R * HH + k];
    }
    // ---- W_ih folded with biases ----
    for (int idx = tid; idx < 16 * VV; idx += THREADS) {
        int r = idx / VV, v = idx - r * VV;
        int R = (r >> 2) * HH + c4 + (r & 3);
        wxb[r * 32 + v] = W_ih[R * VV + v] + b_ih[R] + b_hh[R];
    }
    // ---- stable descending argsort of lengths ----
    if (tid < BB) lens[tid] = lengths[tid];
    __syncthreads();
    if (tid < BB) {
        int L = lens[tid], rk = 0;
        for (int b2 = 0; b2 < BB; b2++) {
            int L2 = lens[b2];
            rk += (L2 > L) || (L2 == L && b2 < tid);
        }
        sorder[rk] = tid;
        slen[rk]   = L;
    }
    // ---- zero this CTA's rows of h buffer 0 ----
    for (int idx = tid; idx < 4 * 2 * BB; idx += THREADS) {
        g_hdup[0][(c4 + (idx >> 7)) * (2 * BB) + (idx & 127)] = 0.f;
    }
    __syncthreads();
    const int T = slen[0];

    // per-thread step-invariant setup
    const int w = tid >> 5, lane = tid & 31;
    const int g = w >> 1, kh = w & 1;             // batch group (8 batches), k half
    const int kq = lane >> 2, bp = lane & 3;      // 8-way k split, batch pair in group
    const int glen = slen[8 * g];                 // group alive while t < glen
    const int kstart = kh * 256 + kq;             // lane's k: kstart + 8*i, i<32

    const int ab = tid & 63, aj = tid >> 6;       // activation mapping (tid<256)
    const int alen = (tid < 256) ? slen[ab] : -1;
    const int* tokrow = tokens + ((tid < 256) ? sorder[ab] : 0) * SS;
    float creg = 0.f;                             // private cell state

    unsigned barno = 1;
    grid_barrier(tid, barno);

    for (int t = 0; t < T; t++) {
        const float* hr = g_hdup[t & 1];
        float*       hw = g_hdup[(t & 1) ^ 1];

        // early token fetch (consumed after sync -> latency hidden)
        int tok = 0;
        if (tid < 256 && t < alen) tok = __ldg(tokrow + t);

        // ---- recurrent matmul: warp = (8 batches) x (16 rows) x (256 k) ----
        if (t < glen) {
            const float4* hp = reinterpret_cast<const float4*>(hr)
                               + (kstart * 32 + 4 * g + bp);            // {h,h,h',h'}
            const float4* wp = reinterpret_cast<const float4*>(wsp) + kstart * 5;
            float2 acc[8][2];
#pragma unroll
            for (int q = 0; q < 8; q++) { acc[q][0] = make_float2(0.f, 0.f);
                                          acc[q][1] = make_float2(0.f, 0.f); }
#pragma unroll 4
            for (int i = 0; i < 32; i++) {
                float4 h4 = __ldcg(hp); hp += 8 * 32;
                float4 w0 = wp[0], w1 = wp[1], w2 = wp[2], w3 = wp[3]; wp += 8 * 5;
                float2 hb0 = make_float2(h4.x, h4.y);
                float2 hb1 = make_float2(h4.z, h4.w);
                ffma2(acc[0][0], make_float2(w0.x, w0.y), hb0);
                ffma2(acc[0][1], make_float2(w0.x, w0.y), hb1);
                ffma2(acc[1][0], make_float2(w0.z, w0.w), hb0);
                ffma2(acc[1][1], make_float2(w0.z, w0.w), hb1);
                ffma2(acc[2][0], make_float2(w1.x, w1.y), hb0);
                ffma2(acc[2][1], make_float2(w1.x, w1.y), hb1);
                ffma2(acc[3][0], make_float2(w1.z, w1.w), hb0);
                ffma2(acc[3][1], make_float2(w1.z, w1.w), hb1);
                ffma2(acc[4][0], make_float2(w2.x, w2.y), hb0);
                ffma2(acc[4][1], make_float2(w2.x, w2.y), hb1);
                ffma2(acc[5][0], make_float2(w2.z, w2.w), hb0);
                ffma2(acc[5][1], make_float2(w2.z, w2.w), hb1);
                ffma2(acc[6][0], make_float2(w3.x, w3.y), hb0);
                ffma2(acc[6][1], make_float2(w3.x, w3.y), hb1);
                ffma2(acc[7][0], make_float2(w3.z, w3.w), hb0);
                ffma2(acc[7][1], make_float2(w3.z, w3.w), hb1);
            }
            // reduce over kq (lane bits 2..4)
#pragma unroll
            for (int m = 4; m <= 16; m <<= 1) {
#pragma unroll
                for (int q = 0; q < 8; q++) {
                    acc[q][0].x += __shfl_xor_sync(0xffffffffu, acc[q][0].x, m);
                    acc[q][0].y += __shfl_xor_sync(0xffffffffu, acc[q][0].y, m);
                    acc[q][1].x += __shfl_xor_sync(0xffffffffu, acc[q][1].x, m);
                    acc[q][1].y += __shfl_xor_sync(0xffffffffu, acc[q][1].y, m);
                }
            }
            if (lane < 4) {  // kq==0 lanes hold sums for batches 8g+2bp, 8g+2bp+1
                float4* gp = reinterpret_cast<float4*>(
                    gredp + kh * (BB * 20) + (8 * g + 2 * bp) * 20);
                gp[0] = make_float4(acc[0][0].x, acc[0][0].y, acc[1][0].x, acc[1][0].y);
                gp[1] = make_float4(acc[2][0].x, acc[2][0].y, acc[3][0].x, acc[3][0].y);
                gp[2] = make_float4(acc[4][0].x, acc[4][0].y, acc[5][0].x, acc[5][0].y);
                gp[3] = make_float4(acc[6][0].x, acc[6][0].y, acc[7][0].x, acc[7][0].y);
                float4* gq = reinterpret_cast<float4*>(
                    gredp + kh * (BB * 20) + (8 * g + 2 * bp + 1) * 20);
                gq[0] = make_float4(acc[0][1].x, acc[0][1].y, acc[1][1].x, acc[1][1].y);
                gq[1] = make_float4(acc[2][1].x, acc[2][1].y, acc[3][1].x, acc[3][1].y);
                gq[2] = make_float4(acc[4][1].x, acc[4][1].y, acc[5][1].x, acc[5][1].y);
                gq[3] = make_float4(acc[6][1].x, acc[6][1].y, acc[7][1].x, acc[7][1].y);
            }
        }
        __syncthreads();

        // ---- gate activations + state update (tid<256: j = hidden 0..3, b) ----
        if (tid < 256) {
            float2* hwp = reinterpret_cast<float2*>(hw + (c4 + aj) * (2 * BB) + 2 * ab);
            if (t < alen) {
                const float* g0 = gredp + ab * 20;
                const float* g1 = gredp + BB * 20 + ab * 20;
                float gi = g0[aj]      + g1[aj]      + wxb[(aj)      * 32 + tok];
                float gf = g0[4 + aj]  + g1[4 + aj]  + wxb[(4 + aj)  * 32 + tok];
                float gg = g0[8 + aj]  + g1[8 + aj]  + wxb[(8 + aj)  * 32 + tok];
                float go = g0[12 + aj] + g1[12 + aj] + wxb[(12 + aj) * 32 + tok];
                float cn = sigm(gf) * creg + sigm(gi) * tanha(gg);
                creg = cn;
                float hv = sigm(go) * tanha(cn);
                __stcg(hwp, make_float2(hv, hv));
            } else if (t == alen) {
                // first frozen step: mirror final h into the other parity buffer;
                // from t+1 on, both buffers hold it and nothing more is written.
                float2 hold = __ldcg(reinterpret_cast<const float2*>(
                    hr + (c4 + aj) * (2 * BB) + 2 * ab));
                __stcg(hwp, hold);
            }
        }

        barno++;
        grid_barrier(tid, barno);
    }

    // ---- final FC: out[s] = fc_w . h_final[:, s] + fc_b (sorted order) ----
    if (blockIdx.x == 0 && tid < 256) {
        const float* hf = g_hdup[T & 1];
        int s = tid >> 2, q = tid & 3;
        float p = 0.f;
        for (int kk = 0; kk < 128; kk++) {
            int k = q * 128 + kk;
            p += __ldcg(&hf[k * (2 * BB) + 2 * s]) * __ldg(&fc_w[k]);
        }
        p += __shfl_down_sync(0xffffffffu, p, 1);
        p += __shfl_down_sync(0xffffffffu, p, 2);
        if (q == 0) out[s] = p + __ldg(fc_b);
    }
}

extern "C" void kernel_launch(void* const* d_in, const int* in_sizes, int n_in,
                              void* d_out, int out_size) {
    const int*   tokens  = (const int*)d_in[0];
    const int*   lengths = (const int*)d_in[1];
    const float* W_ih    = (const float*)d_in[2];
    const float* W_hh    = (const float*)d_in[3];
    const float* b_ih    = (const float*)d_in[4];
    const float* b_hh    = (const float*)d_in[5];
    const float* fc_w    = (const float*)d_in[6];
    const float* fc_b    = (const float*)d_in[7];
    float* out = (float*)d_out;

    cudaFuncSetAttribute(lstm_persistent_kernel,
                         cudaFuncAttributeMaxDynamicSharedMemorySize, SMEM_BYTES);
    init_barrier_kernel<<<1, 1>>>();
    lstm_persistent_kernel<<<NB, THREADS, SMEM_BYTES>>>(
        tokens, lengths, W_ih, W_hh, b_ih, b_hh, fc_w, fc_b, out);
}

// round 3
// speedup vs baseline: 1.5430x; 1.1500x over previous
#include <cuda_runtime.h>

#define NB      128     // persistent CTAs (< 148 SMs -> co-resident, barrier safe)
#define THREADS 512     // 16 warps, 4 per SMSP
#define BB      64      // batch
#define SS      2048    // seq len
#define HH      512     // hidden
#define VV      25      // vocab

// h double buffer, batch-duplicated: [parity][k][2*BB], slot 2b,2b+1 both = h[k][b]
__device__ float g_hdup[2][HH * 2 * BB];
__device__ unsigned g_count;

__global__ void init_barrier_kernel() { g_count = 0u; }

// packed fp32x2 FMA (Blackwell): acc += x * y elementwise on 2 lanes
__device__ __forceinline__ void ffma2(float2& a, const float2 x, const float2 y) {
    asm("fma.rn.f32x2 %0, %1, %2, %0;"
        : "+l"(reinterpret_cast<unsigned long long&>(a))
        : "l"(reinterpret_cast<const unsigned long long&>(x)),
          "l"(reinterpret_cast<const unsigned long long&>(y)));
}

// fast, saturation-safe sigmoid / tanh
__device__ __forceinline__ float sigm(float x) {
    float e = __expf(-x);
    return __fdividef(1.f, 1.f + e);
}
__device__ __forceinline__ float tanha(float x) {
    return fmaf(2.f, sigm(2.f * x), -1.f);
}

// grid barrier: REDG release arrive + direct acquire-poll of one counter.
// bar.sync gives happens-before from all block threads to tid0's release;
// ld.acquire + trailing bar.sync publishes h to all block threads.
__device__ __forceinline__ void grid_barrier(int tid, unsigned barno) {
    __syncthreads();
    if (tid == 0) {
        asm volatile("red.release.gpu.global.add.u32 [%0], 1;"
                     :: "l"(&g_count) : "memory");
        unsigned v;
        do {
            asm volatile("ld.acquire.gpu.global.u32 %0, [%1];"
                         : "=r"(v) : "l"(&g_count));
        } while (v < barno * (unsigned)NB);
    }
    __syncthreads();
}

// dynamic smem layout (floats)
#define WSP_FLOATS  (HH * 20)          // [k][20]: 16 rows (r=gate*4+j) + 4 pad
#define WXB_FLOATS  (16 * 32)          // [r][vocab padded 32], biases folded
#define GRD_FLOATS  (2 * BB * 20)      // [kh][batch][20]: 16 gate rows + pad
#define SMEM_BYTES  ((WSP_FLOATS + WXB_FLOATS + GRD_FLOATS + 3 * BB) * 4)

__global__ void __launch_bounds__(THREADS, 1) lstm_persistent_kernel(
    const int* __restrict__ tokens, const int* __restrict__ lengths,
    const float* __restrict__ W_ih, const float* __restrict__ W_hh,
    const float* __restrict__ b_ih, const float* __restrict__ b_hh,
    const float* __restrict__ fc_w, const float* __restrict__ fc_b,
    float* __restrict__ out)
{
    extern __shared__ char smem_raw[];
    float* wsp   = reinterpret_cast<float*>(smem_raw);
    float* wxb   = wsp + WSP_FLOATS;
    float* gredp = wxb + WXB_FLOATS;              // [kh*64*20 + b*20 + r]
    int*   slen   = reinterpret_cast<int*>(gredp + GRD_FLOATS);
    int*   sorder = slen + BB;
    int*   lens   = sorder + BB;

    const int tid = threadIdx.x;
    const int c4  = blockIdx.x * 4;   // this CTA's 4 hidden dims

    // ---- W_hh chunk into smem: wsp[k*20 + r], r = gate*4 + j ----
    for (int idx = tid; idx < 16 * HH; idx += THREADS) {
        int r = idx >> 9, k = idx & (HH - 1);
        int R = (r >> 2) * HH + c4 + (r & 3);
        wsp[k * 20 + r] = W_hh[R * HH + k];
    }
    // ---- W_ih folded with biases ----
    for (int idx = tid; idx < 16 * VV; idx += THREADS) {
        int r = idx / VV, v = idx - r * VV;
        int R = (r >> 2) * HH + c4 + (r & 3);
        wxb[r * 32 + v] = W_ih[R * VV + v] + b_ih[R] + b_hh[R];
    }
    // ---- stable descending argsort of lengths ----
    if (tid < BB) lens[tid] = lengths[tid];
    __syncthreads();
    if (tid < BB) {
        int L = lens[tid], rk = 0;
        for (int b2 = 0; b2 < BB; b2++) {
            int L2 = lens[b2];
            rk += (L2 > L) || (L2 == L && b2 < tid);
        }
        sorder[rk] = tid;
        slen[rk]   = L;
    }
    // ---- zero this CTA's rows of h buffer 0 ----
    for (int idx = tid; idx < 4 * 2 * BB; idx += THREADS) {
        g_hdup[0][(c4 + (idx >> 7)) * (2 * BB) + (idx & 127)] = 0.f;
    }
    __syncthreads();
    const int T = slen[0];

    // per-warp step-invariant setup
    const int w = tid >> 5, lane = tid & 31;
    const int g = w >> 1, kh = w & 1;             // batch group (8 batches), k half
    const int kq = lane >> 2, bp = lane & 3;      // 8-way k split, batch pair in group
    const int glen = slen[8 * g];                 // group max length
    const int kstart = kh * 256 + kq;

    // activation mapping (kh==0 warps only): lane -> (j, b)
    const int aj = lane >> 3, ab = lane & 7;
    const int sb = 8 * g + ab;                    // batch slot
    const int alen = slen[sb];
    const int* tokrow = tokens + sorder[sb] * SS;
    float creg = 0.f;                             // private cell state (kh==0 lanes)

    unsigned barno = 1;
    grid_barrier(tid, barno);

    for (int t = 0; t < T; t++) {
        const float* hr = g_hdup[t & 1];
        float*       hw = g_hdup[(t & 1) ^ 1];

        // early token fetch (consumed after named bar -> latency hidden)
        int tok = 0;
        if (kh == 0 && t < alen) tok = __ldg(tokrow + t);

        // ---- recurrent matmul: warp pair = (8 batches) x (16 rows) x (512 k) ----
        if (t < glen) {
            const float4* hp = reinterpret_cast<const float4*>(hr)
                               + (kstart * 32 + 4 * g + bp);            // {h,h,h',h'}
            const float4* wp = reinterpret_cast<const float4*>(wsp) + kstart * 5;
            float2 acc[8][2];
#pragma unroll
            for (int q = 0; q < 8; q++) { acc[q][0] = make_float2(0.f, 0.f);
                                          acc[q][1] = make_float2(0.f, 0.f); }
#pragma unroll 4
            for (int i = 0; i < 32; i++) {
                float4 h4 = __ldcg(hp); hp += 8 * 32;
                float4 w0 = wp[0], w1 = wp[1], w2 = wp[2], w3 = wp[3]; wp += 8 * 5;
                float2 hb0 = make_float2(h4.x, h4.y);
                float2 hb1 = make_float2(h4.z, h4.w);
                ffma2(acc[0][0], make_float2(w0.x, w0.y), hb0);
                ffma2(acc[0][1], make_float2(w0.x, w0.y), hb1);
                ffma2(acc[1][0], make_float2(w0.z, w0.w), hb0);
                ffma2(acc[1][1], make_float2(w0.z, w0.w), hb1);
                ffma2(acc[2][0], make_float2(w1.x, w1.y), hb0);
                ffma2(acc[2][1], make_float2(w1.x, w1.y), hb1);
                ffma2(acc[3][0], make_float2(w1.z, w1.w), hb0);
                ffma2(acc[3][1], make_float2(w1.z, w1.w), hb1);
                ffma2(acc[4][0], make_float2(w2.x, w2.y), hb0);
                ffma2(acc[4][1], make_float2(w2.x, w2.y), hb1);
                ffma2(acc[5][0], make_float2(w2.z, w2.w), hb0);
                ffma2(acc[5][1], make_float2(w2.z, w2.w), hb1);
                ffma2(acc[6][0], make_float2(w3.x, w3.y), hb0);
                ffma2(acc[6][1], make_float2(w3.x, w3.y), hb1);
                ffma2(acc[7][0], make_float2(w3.z, w3.w), hb0);
                ffma2(acc[7][1], make_float2(w3.z, w3.w), hb1);
            }
            // reduce over kq (lane bits 2..4)
#pragma unroll
            for (int m = 4; m <= 16; m <<= 1) {
#pragma unroll
                for (int q = 0; q < 8; q++) {
                    acc[q][0].x += __shfl_xor_sync(0xffffffffu, acc[q][0].x, m);
                    acc[q][0].y += __shfl_xor_sync(0xffffffffu, acc[q][0].y, m);
                    acc[q][1].x += __shfl_xor_sync(0xffffffffu, acc[q][1].x, m);
                    acc[q][1].y += __shfl_xor_sync(0xffffffffu, acc[q][1].y, m);
                }
            }
            if (lane < 4) {  // kq==0 lanes hold sums for batches 8g+2bp, 8g+2bp+1
                float4* gp = reinterpret_cast<float4*>(
                    gredp + kh * (BB * 20) + (8 * g + 2 * bp) * 20);
                gp[0] = make_float4(acc[0][0].x, acc[0][0].y, acc[1][0].x, acc[1][0].y);
                gp[1] = make_float4(acc[2][0].x, acc[2][0].y, acc[3][0].x, acc[3][0].y);
                gp[2] = make_float4(acc[4][0].x, acc[4][0].y, acc[5][0].x, acc[5][0].y);
                gp[3] = make_float4(acc[6][0].x, acc[6][0].y, acc[7][0].x, acc[7][0].y);
                float4* gq = reinterpret_cast<float4*>(
                    gredp + kh * (BB * 20) + (8 * g + 2 * bp + 1) * 20);
                gq[0] = make_float4(acc[0][1].x, acc[0][1].y, acc[1][1].x, acc[1][1].y);
                gq[1] = make_float4(acc[2][1].x, acc[2][1].y, acc[3][1].x, acc[3][1].y);
                gq[2] = make_float4(acc[4][1].x, acc[4][1].y, acc[5][1].x, acc[5][1].y);
                gq[3] = make_float4(acc[6][1].x, acc[6][1].y, acc[7][1].x, acc[7][1].y);
            }
            // pair sync: both k-half warps' partials visible (named barrier, 64 thr)
            asm volatile("bar.sync %0, 64;" :: "r"(g + 1) : "memory");
        }

        // ---- activation + state update: kh==0 warp, lane = (j in 0..3, b in 0..7) ----
        if (kh == 0 && t <= glen) {
            float2* hwp = reinterpret_cast<float2*>(hw + (c4 + aj) * (2 * BB) + 2 * sb);
            if (t < alen) {
                const float* g0 = gredp + sb * 20;
                const float* g1 = gredp + BB * 20 + sb * 20;
                float gi = g0[aj]      + g1[aj]      + wxb[(aj)      * 32 + tok];
                float gf = g0[4 + aj]  + g1[4 + aj]  + wxb[(4 + aj)  * 32 + tok];
                float gg = g0[8 + aj]  + g1[8 + aj]  + wxb[(8 + aj)  * 32 + tok];
                float go = g0[12 + aj] + g1[12 + aj] + wxb[(12 + aj) * 32 + tok];
                float cn = sigm(gf) * creg + sigm(gi) * tanha(gg);
                creg = cn;
                float hv = sigm(go) * tanha(cn);
                __stcg(hwp, make_float2(hv, hv));
            } else if (t == alen) {
                // first frozen step: mirror final h into the other parity buffer
                float2 hold = __ldcg(reinterpret_cast<const float2*>(
                    hr + (c4 + aj) * (2 * BB) + 2 * sb));
                __stcg(hwp, hold);
            }
        }

        barno++;
        grid_barrier(tid, barno);
    }

    // ---- final FC: out[s] = fc_w . h_final[:, s] + fc_b (sorted order) ----
    if (blockIdx.x == 0 && tid < 256) {
        const float* hf = g_hdup[T & 1];
        int s = tid >> 2, q = tid & 3;
        float p = 0.f;
        for (int kk = 0; kk < 128; kk++) {
            int k = q * 128 + kk;
            p += __ldcg(&hf[k * (2 * BB) + 2 * s]) * __ldg(&fc_w[k]);
        }
        p += __shfl_down_sync(0xffffffffu, p, 1);
        p += __shfl_down_sync(0xffffffffu, p, 2);
        if (q == 0) out[s] = p + __ldg(fc_b);
    }
}

extern "C" void kernel_launch(void* const* d_in, const int* in_sizes, int n_in,
                              void* d_out, int out_size) {
    const int*   tokens  = (const int*)d_in[0];
    const int*   lengths = (const int*)d_in[1];
    const float* W_ih    = (const float*)d_in[2];
    const float* W_hh    = (const float*)d_in[3];
    const float* b_ih    = (const float*)d_in[4];
    const float* b_hh    = (const float*)d_in[5];
    const float* fc_w    = (const float*)d_in[6];
    const float* fc_b    = (const float*)d_in[7];
    float* out = (float*)d_out;

    cudaFuncSetAttribute(lstm_persistent_kernel,
                         cudaFuncAttributeMaxDynamicSharedMemorySize, SMEM_BYTES);
    init_barrier_kernel<<<1, 1>>>();
    lstm_persistent_kernel<<<NB, THREADS, SMEM_BYTES>>>(
        tokens, lengths, W_ih, W_hh, b_ih, b_hh, fc_w, fc_b, out);
}